// round 2
// baseline (speedup 1.0000x reference)
#include <cuda_runtime.h>
#include <math.h>

// Problem constants
#define Bv 2
#define Sv 2048
#define Dv 1024
#define Hv 16
#define DKv 64
#define Nv (Bv * Sv)   // 4096 rows

// Scratch (device globals — no cudaMalloc allowed)
__device__ float g_q[(size_t)Nv * Dv];
__device__ float g_k[(size_t)Nv * Dv];
__device__ float g_v[(size_t)Nv * Dv];
__device__ float g_attn[(size_t)Nv * Dv];

// ---------------------------------------------------------------------------
// Tiled GEMM: Y[n][e] = sum_d X[n][d] * W[e][d]   (X:[N,1024], W:[1024,1024])
// mode: 0 = plain store, 1 = RoPE epilogue (K), 2 = RoPE + 1/sqrt(DK) (Q)
// Block: 64x64 tile, 256 threads, each thread 4x4 micro-tile, BK=16.
// ---------------------------------------------------------------------------
__global__ __launch_bounds__(256) void gemm_kernel(
    const float* __restrict__ X, const float* __restrict__ W,
    float* __restrict__ Y, const int* __restrict__ tp, int mode)
{
    __shared__ float As[16][68];
    __shared__ float Bs[16][68];

    const int tid = threadIdx.x;
    const int tx = tid & 15;
    const int ty = tid >> 4;
    const int n0 = blockIdx.y * 64;
    const int e0 = blockIdx.x * 64;

    // loader mapping: 256 threads x float4 = 64 rows x 16 k
    const int lrow = tid >> 2;          // 0..63
    const int lcol = (tid & 3) << 2;    // 0,4,8,12

    const float* xp = X + (size_t)(n0 + lrow) * Dv + lcol;
    const float* wp = W + (size_t)(e0 + lrow) * Dv + lcol;

    float acc[4][4] = {};

    for (int k0 = 0; k0 < Dv; k0 += 16) {
        float4 a = *(const float4*)(xp + k0);
        float4 b = *(const float4*)(wp + k0);
        As[lcol + 0][lrow] = a.x; As[lcol + 1][lrow] = a.y;
        As[lcol + 2][lrow] = a.z; As[lcol + 3][lrow] = a.w;
        Bs[lcol + 0][lrow] = b.x; Bs[lcol + 1][lrow] = b.y;
        Bs[lcol + 2][lrow] = b.z; Bs[lcol + 3][lrow] = b.w;
        __syncthreads();

        #pragma unroll
        for (int k = 0; k < 16; ++k) {
            float4 av = *(const float4*)&As[k][ty * 4];
            float4 bv = *(const float4*)&Bs[k][tx * 4];
            float ar[4] = {av.x, av.y, av.z, av.w};
            float br[4] = {bv.x, bv.y, bv.z, bv.w};
            #pragma unroll
            for (int i = 0; i < 4; ++i)
                #pragma unroll
                for (int j = 0; j < 4; ++j)
                    acc[i][j] = fmaf(ar[i], br[j], acc[i][j]);
        }
        __syncthreads();
    }

    if (mode == 0) {
        #pragma unroll
        for (int i = 0; i < 4; ++i) {
            float4 o = make_float4(acc[i][0], acc[i][1], acc[i][2], acc[i][3]);
            *(float4*)&Y[(size_t)(n0 + ty * 4 + i) * Dv + e0 + tx * 4] = o;
        }
    } else {
        const float qscale = (mode == 2) ? 0.125f : 1.0f;  // 1/sqrt(64)
        // ln(10000)/32
        const float LN_TH_OVER_HALFDK = 0.2878231366242557f;
        #pragma unroll
        for (int i = 0; i < 4; ++i) {
            int n = n0 + ty * 4 + i;
            int s = n & (Sv - 1);
            float pos = (float)tp[s];
            #pragma unroll
            for (int jp = 0; jp < 2; ++jp) {
                int j = jp * 2;
                int e = e0 + tx * 4 + j;
                int idx = e & (DKv - 1);
                int p = idx >> 1;
                float inv = expf(-LN_TH_OVER_HALFDK * (float)p);
                float ang = pos * inv;
                float sn, cs;
                sincosf(ang, &sn, &cs);
                float t0 = acc[i][j], t1 = acc[i][j + 1];
                float o0 = (cs * t0 - sn * t1) * qscale;
                float o1 = (sn * t0 + cs * t1) * qscale;
                size_t base = (size_t)n * Dv + e;
                Y[base] = o0;
                Y[base + 1] = o1;
            }
        }
    }
}

// ---------------------------------------------------------------------------
// Flash-style causal attention. One block = (b, h, 64 q-rows).
// Q pre-scaled by 1/sqrt(DK). Online softmax, fp32 accumulate.
// ---------------------------------------------------------------------------
__global__ __launch_bounds__(256) void attn_kernel()
{
    extern __shared__ float sm[];
    float* Qt = sm;                 // [64 d][68]: Qt[d*68 + r]
    float* Kt = sm + 64 * 68;       // [64 d][68]: Kt[d*68 + c]
    float* Vs = sm + 2 * 64 * 68;   // [64 c][68]: Vs[c*68 + d]
    float* Ps = sm + 3 * 64 * 68;   // [64 r][68]: Ps[r*68 + c]

    const int tid = threadIdx.x;
    const int tx = tid & 15;
    const int ty = tid >> 4;
    const int jt = blockIdx.x;   // q tile index
    const int h  = blockIdx.y;
    const int b  = blockIdx.z;
    const int q0 = jt * 64;

    const int lrow = tid >> 2;          // 0..63 (tile row)
    const int lcol = (tid & 3) << 2;    // 0,4,8,12 (base d offset)

    // Load FULL Q tile (64 rows x 64 d), transposed to d-major.
    // Each thread loads 4 float4s: d = c0 + lcol, c0 in {0,16,32,48}.
    {
        const float* qg = g_q + ((size_t)(b * Sv + q0 + lrow)) * Dv + h * 64;
        #pragma unroll
        for (int c0 = 0; c0 < 64; c0 += 16) {
            int col = c0 + lcol;
            float4 a = *(const float4*)(qg + col);
            Qt[(col + 0) * 68 + lrow] = a.x;
            Qt[(col + 1) * 68 + lrow] = a.y;
            Qt[(col + 2) * 68 + lrow] = a.z;
            Qt[(col + 3) * 68 + lrow] = a.w;
        }
    }

    float m[4], l[4], acc[4][4];
    #pragma unroll
    for (int i = 0; i < 4; ++i) {
        m[i] = -INFINITY;
        l[i] = 0.f;
        #pragma unroll
        for (int j = 0; j < 4; ++j) acc[i][j] = 0.f;
    }

    for (int j = 0; j <= jt; ++j) {
        __syncthreads();  // all threads done with Kt/Vs/Ps before overwrite
        {
            const float* kg = g_k + (size_t)(b * Sv + j * 64 + lrow) * Dv + h * 64;
            const float* vg = g_v + (size_t)(b * Sv + j * 64 + lrow) * Dv + h * 64;
            #pragma unroll
            for (int c0 = 0; c0 < 64; c0 += 16) {
                int col = c0 + lcol;
                float4 kk = *(const float4*)(kg + col);
                Kt[(col + 0) * 68 + lrow] = kk.x;
                Kt[(col + 1) * 68 + lrow] = kk.y;
                Kt[(col + 2) * 68 + lrow] = kk.z;
                Kt[(col + 3) * 68 + lrow] = kk.w;
                float4 vv = *(const float4*)(vg + col);
                *(float4*)&Vs[lrow * 68 + col] = vv;
            }
        }
        __syncthreads();

        // S = Q K^T (64x64 distributed 4x4 per thread)
        float sacc[4][4] = {};
        #pragma unroll 8
        for (int d = 0; d < 64; ++d) {
            float4 av = *(const float4*)&Qt[d * 68 + ty * 4];
            float4 bv = *(const float4*)&Kt[d * 68 + tx * 4];
            float ar[4] = {av.x, av.y, av.z, av.w};
            float br[4] = {bv.x, bv.y, bv.z, bv.w};
            #pragma unroll
            for (int i = 0; i < 4; ++i)
                #pragma unroll
                for (int jj = 0; jj < 4; ++jj)
                    sacc[i][jj] = fmaf(ar[i], br[jj], sacc[i][jj]);
        }

        // causal mask on the diagonal tile
        if (j == jt) {
            #pragma unroll
            for (int i = 0; i < 4; ++i)
                #pragma unroll
                for (int jj = 0; jj < 4; ++jj)
                    if (tx * 4 + jj > ty * 4 + i) sacc[i][jj] = -INFINITY;
        }

        // online softmax per row (row spans 16 lanes of a half-warp)
        #pragma unroll
        for (int i = 0; i < 4; ++i) {
            float t = fmaxf(fmaxf(sacc[i][0], sacc[i][1]),
                            fmaxf(sacc[i][2], sacc[i][3]));
            #pragma unroll
            for (int o = 1; o < 16; o <<= 1)
                t = fmaxf(t, __shfl_xor_sync(0xffffffffu, t, o));
            float mnew = fmaxf(m[i], t);
            float scale = __expf(m[i] - mnew);
            float pr[4];
            float sum = 0.f;
            #pragma unroll
            for (int jj = 0; jj < 4; ++jj) {
                pr[jj] = __expf(sacc[i][jj] - mnew);
                sum += pr[jj];
            }
            *(float4*)&Ps[(ty * 4 + i) * 68 + tx * 4] =
                make_float4(pr[0], pr[1], pr[2], pr[3]);
            #pragma unroll
            for (int o = 1; o < 16; o <<= 1)
                sum += __shfl_xor_sync(0xffffffffu, sum, o);
            l[i] = l[i] * scale + sum;
            m[i] = mnew;
            #pragma unroll
            for (int jj = 0; jj < 4; ++jj) acc[i][jj] *= scale;
        }
        __syncthreads();

        // O += P V
        #pragma unroll 8
        for (int c = 0; c < 64; ++c) {
            float4 bv = *(const float4*)&Vs[c * 68 + tx * 4];
            #pragma unroll
            for (int i = 0; i < 4; ++i) {
                float a = Ps[(ty * 4 + i) * 68 + c];
                acc[i][0] = fmaf(a, bv.x, acc[i][0]);
                acc[i][1] = fmaf(a, bv.y, acc[i][1]);
                acc[i][2] = fmaf(a, bv.z, acc[i][2]);
                acc[i][3] = fmaf(a, bv.w, acc[i][3]);
            }
        }
    }

    // finalize and store to g_attn [B,S,D]
    #pragma unroll
    for (int i = 0; i < 4; ++i) {
        float invl = 1.f / l[i];
        float4 o = make_float4(acc[i][0] * invl, acc[i][1] * invl,
                               acc[i][2] * invl, acc[i][3] * invl);
        *(float4*)&g_attn[(size_t)(b * Sv + q0 + ty * 4 + i) * Dv + h * 64 + tx * 4] = o;
    }
}

// ---------------------------------------------------------------------------
extern "C" void kernel_launch(void* const* d_in, const int* in_sizes, int n_in,
                              void* d_out, int out_size)
{
    const float* x  = (const float*)d_in[0];
    const int*   tp = (const int*)d_in[1];
    const float* wq = (const float*)d_in[2];
    const float* wk = (const float*)d_in[3];
    const float* wv = (const float*)d_in[4];
    const float* wo = (const float*)d_in[5];
    float* out = (float*)d_out;

    float *pq, *pk, *pv, *pa;
    cudaGetSymbolAddress((void**)&pq, g_q);
    cudaGetSymbolAddress((void**)&pk, g_k);
    cudaGetSymbolAddress((void**)&pv, g_v);
    cudaGetSymbolAddress((void**)&pa, g_attn);

    dim3 gg(Dv / 64, Nv / 64);   // (16, 64)

    gemm_kernel<<<gg, 256>>>(x, wq, pq, tp, 2);  // Q: RoPE + scale
    gemm_kernel<<<gg, 256>>>(x, wk, pk, tp, 1);  // K: RoPE
    gemm_kernel<<<gg, 256>>>(x, wv, pv, tp, 0);  // V

    size_t smem = 4 * 64 * 68 * sizeof(float);   // 69632 B
    cudaFuncSetAttribute(attn_kernel, cudaFuncAttributeMaxDynamicSharedMemorySize,
                         (int)smem);
    attn_kernel<<<dim3(Sv / 64, Hv, Bv), 256, smem>>>();

    gemm_kernel<<<gg, 256>>>(pa, wo, out, tp, 0); // output projection
}

// round 4
// speedup vs baseline: 1.5416x; 1.5416x over previous
#include <cuda_runtime.h>
#include <cuda_bf16.h>
#include <math.h>
#include <stdint.h>

// Problem constants
#define Bv 2
#define Sv 2048
#define Dv 1024
#define Hv 16
#define DKv 64
#define Nv (Bv * Sv)     // 4096 rows
#define TKv 3072         // split-bf16 concatenated K
#define SLABK 64         // bf16 K per SMEM slab (128 bytes/row, SW128)
#define NSLAB (TKv / SLABK)  // 48

// ---------------------------------------------------------------------------
// Scratch (device globals — no cudaMalloc allowed)
// ---------------------------------------------------------------------------
__device__ float g_q[(size_t)Nv * Dv];
__device__ float g_k[(size_t)Nv * Dv];
__device__ float g_v[(size_t)Nv * Dv];
__device__ float g_attn[(size_t)Nv * Dv];
__device__ __nv_bfloat16 g_xs[(size_t)Nv * TKv];          // [Xhi|Xhi|Xlo]
__device__ __nv_bfloat16 g_as[(size_t)Nv * TKv];          // attn split
__device__ __nv_bfloat16 g_ws[4][(size_t)Dv * TKv];       // [Whi|Wlo|Whi] x4

__device__ __forceinline__ uint32_t smem_to_u32(const void* p) {
    uint32_t a;
    asm("{ .reg .u64 t; cvta.to.shared.u64 t, %1; cvt.u32.u64 %0, t; }"
        : "=r"(a) : "l"(p));
    return a;
}
#define SW128(off) ((off) ^ (((off) >> 3) & 0x70))

// ---------------------------------------------------------------------------
// Split fp32 -> [hi|hi|lo] (bmode=0, activations) or [hi|lo|hi] (bmode=1, wts)
// ---------------------------------------------------------------------------
__global__ __launch_bounds__(256) void split_kernel(
    const float* __restrict__ src, __nv_bfloat16* __restrict__ dst,
    int total, int bmode)
{
    int gid = blockIdx.x * blockDim.x + threadIdx.x;
    int e0 = gid * 4;
    if (e0 >= total) return;
    int r = e0 >> 10;
    int c = e0 & 1023;
    float4 v = *(const float4*)(src + e0);

    __nv_bfloat16 h0 = __float2bfloat16(v.x);
    __nv_bfloat16 h1 = __float2bfloat16(v.y);
    __nv_bfloat16 h2 = __float2bfloat16(v.z);
    __nv_bfloat16 h3 = __float2bfloat16(v.w);
    __nv_bfloat16 l0 = __float2bfloat16(v.x - __bfloat162float(h0));
    __nv_bfloat16 l1 = __float2bfloat16(v.y - __bfloat162float(h1));
    __nv_bfloat16 l2 = __float2bfloat16(v.z - __bfloat162float(h2));
    __nv_bfloat16 l3 = __float2bfloat16(v.w - __bfloat162float(h3));

    __nv_bfloat162 hp0 = {h0, h1}, hp1 = {h2, h3};
    __nv_bfloat162 lp0 = {l0, l1}, lp1 = {l2, l3};
    uint2 hu, lu;
    hu.x = *(uint32_t*)&hp0; hu.y = *(uint32_t*)&hp1;
    lu.x = *(uint32_t*)&lp0; lu.y = *(uint32_t*)&lp1;

    size_t base = (size_t)r * TKv + c;
    *(uint2*)(dst + base)        = hu;
    *(uint2*)(dst + base + 1024) = bmode ? lu : hu;
    *(uint2*)(dst + base + 2048) = bmode ? hu : lu;
}

// ---------------------------------------------------------------------------
// mma.sync bf16 GEMM: Y[m][e] = sum_k' A[m][k'] * Bw[e][k'], K'=3072.
// CTA tile 128x128, 8 warps (4m x 2n), warp tile 32x64, BK=64 slabs.
// SMEM SW128-swizzled, register-prefetch double buffer.
// mode: 0 plain, 1 RoPE (K), 2 RoPE + 1/8 (Q)
// ---------------------------------------------------------------------------
__device__ __forceinline__ void ldm_x4(uint32_t* r, uint32_t addr) {
    asm volatile("ldmatrix.sync.aligned.m8n8.x4.shared.b16 {%0,%1,%2,%3}, [%4];"
        : "=r"(r[0]), "=r"(r[1]), "=r"(r[2]), "=r"(r[3]) : "r"(addr));
}
__device__ __forceinline__ void mma_16816(float* d, const uint32_t* a,
                                          const uint32_t* b) {
    asm volatile(
        "mma.sync.aligned.m16n8k16.row.col.f32.bf16.bf16.f32 "
        "{%0,%1,%2,%3}, {%4,%5,%6,%7}, {%8,%9}, {%0,%1,%2,%3};"
        : "+f"(d[0]), "+f"(d[1]), "+f"(d[2]), "+f"(d[3])
        : "r"(a[0]), "r"(a[1]), "r"(a[2]), "r"(a[3]), "r"(b[0]), "r"(b[1]));
}

__global__ __launch_bounds__(256, 1) void gemm_mma(
    const __nv_bfloat16* __restrict__ A, const __nv_bfloat16* __restrict__ Bw,
    float* __restrict__ Y, const int* __restrict__ tp, int mode)
{
    extern __shared__ char smraw[];
    uint32_t smem_u = smem_to_u32(smraw);
    uint32_t base = (smem_u + 1023u) & ~1023u;   // 1KB align
    char* sm = smraw + (base - smem_u);
    // buffers: A0 @0, B0 @16K, A1 @32K, B1 @48K (each 128x64 bf16 = 16KB)

    const int tid = threadIdx.x;
    const int wid = tid >> 5;
    const int lane = tid & 31;
    const int wm = wid >> 1;          // 0..3
    const int wn = wid & 1;           // 0..1
    const int m0 = blockIdx.y * 128;
    const int e0 = blockIdx.x * 128;

    // loader mapping: thread -> (row, 16B chunk) x4 iters
    const int g2 = lane >> 2;         // mma group row
    const int t4 = lane & 3;

    const __nv_bfloat16* Ag = A + (size_t)m0 * TKv;
    const __nv_bfloat16* Bg = Bw + (size_t)e0 * TKv;

    float acc[2][8][4];
    #pragma unroll
    for (int i = 0; i < 2; ++i)
        #pragma unroll
        for (int j = 0; j < 8; ++j)
            #pragma unroll
            for (int k = 0; k < 4; ++k) acc[i][j][k] = 0.f;

    // ldmatrix per-lane row/khalf (same formula for A and B tiles)
    const int lrow = lane & 15;
    const int lkoff = ((lane >> 4) & 1) * 16;   // byte offset within 32B kstep

    // prologue: load slab 0 into buffer 0
    {
        #pragma unroll
        for (int kk = 0; kk < 4; ++kk) {
            int idx = kk * 256 + tid;
            int r = idx >> 3, c = idx & 7;
            size_t goff = (size_t)r * TKv + c * 8;
            uint32_t so = SW128((uint32_t)(r * 128 + c * 16));
            *(uint4*)(sm + so)         = *(const uint4*)(Ag + goff);
            *(uint4*)(sm + 16384 + so) = *(const uint4*)(Bg + goff);
        }
    }
    __syncthreads();

    for (int s = 0; s < NSLAB; ++s) {
        const int cur = s & 1;
        char* pA = sm + cur * 32768;
        char* pB = sm + cur * 32768 + 16384;

        // prefetch next slab into registers
        uint4 pa[4], pb[4];
        if (s + 1 < NSLAB) {
            #pragma unroll
            for (int kk = 0; kk < 4; ++kk) {
                int idx = kk * 256 + tid;
                int r = idx >> 3, c = idx & 7;
                size_t goff = (size_t)r * TKv + (s + 1) * SLABK + c * 8;
                pa[kk] = *(const uint4*)(Ag + goff);
                pb[kk] = *(const uint4*)(Bg + goff);
            }
        }

        // compute 4 k-steps of 16
        const uint32_t pAu = smem_to_u32(pA);
        const uint32_t pBu = smem_to_u32(pB);
        #pragma unroll
        for (int ks = 0; ks < 4; ++ks) {
            const uint32_t kbyte = ks * 32 + lkoff;
            uint32_t afr[2][4], bfr[4][4];
            #pragma unroll
            for (int am = 0; am < 2; ++am) {
                uint32_t off = (uint32_t)((wm * 32 + am * 16 + lrow) * 128) + kbyte;
                ldm_x4(afr[am], pAu + SW128(off));
            }
            #pragma unroll
            for (int bn = 0; bn < 4; ++bn) {
                uint32_t off = (uint32_t)((wn * 64 + bn * 16 + lrow) * 128) + kbyte;
                ldm_x4(bfr[bn], pBu + SW128(off));
            }
            #pragma unroll
            for (int am = 0; am < 2; ++am)
                #pragma unroll
                for (int bn = 0; bn < 4; ++bn) {
                    uint32_t blo[2] = {bfr[bn][0], bfr[bn][2]};
                    uint32_t bhi[2] = {bfr[bn][1], bfr[bn][3]};
                    mma_16816(acc[am][bn * 2],     afr[am], blo);
                    mma_16816(acc[am][bn * 2 + 1], afr[am], bhi);
                }
        }
        __syncthreads();

        if (s + 1 < NSLAB) {
            char* nA = sm + ((s + 1) & 1) * 32768;
            char* nB = nA + 16384;
            #pragma unroll
            for (int kk = 0; kk < 4; ++kk) {
                int idx = kk * 256 + tid;
                int r = idx >> 3, c = idx & 7;
                uint32_t so = SW128((uint32_t)(r * 128 + c * 16));
                *(uint4*)(nA + so) = pa[kk];
                *(uint4*)(nB + so) = pb[kk];
            }
            __syncthreads();
        }
    }

    // epilogue: acc[am][bn8][0..3] -> D rows (g2, g2+8), cols (2t, 2t+1)
    const float qs = (mode == 2) ? 0.125f : 1.0f;
    const float LTH = 0.2878231366242557f;   // ln(10000)/32
    #pragma unroll
    for (int am = 0; am < 2; ++am) {
        #pragma unroll
        for (int half = 0; half < 2; ++half) {
            int m = m0 + wm * 32 + am * 16 + g2 + half * 8;
            float* yr = Y + (size_t)m * Dv;
            float pos = (mode != 0) ? (float)tp[m & (Sv - 1)] : 0.f;
            #pragma unroll
            for (int bn = 0; bn < 8; ++bn) {
                int e = e0 + wn * 64 + bn * 8 + t4 * 2;
                float d0 = acc[am][bn][half * 2];
                float d1 = acc[am][bn][half * 2 + 1];
                if (mode != 0) {
                    int p = (e & (DKv - 1)) >> 1;
                    float inv = expf(-LTH * (float)p);
                    float sn, cs;
                    sincosf(pos * inv, &sn, &cs);
                    float o0 = (cs * d0 - sn * d1) * qs;
                    float o1 = (sn * d0 + cs * d1) * qs;
                    d0 = o0; d1 = o1;
                }
                *(float2*)(yr + e) = make_float2(d0, d1);
            }
        }
    }
}

// ---------------------------------------------------------------------------
// Flash-style causal attention (unchanged, known-good). Block = (b,h,64 rows).
// ---------------------------------------------------------------------------
__global__ __launch_bounds__(256) void attn_kernel()
{
    extern __shared__ float smf[];
    float* Qt = smf;
    float* Kt = smf + 64 * 68;
    float* Vs = smf + 2 * 64 * 68;
    float* Ps = smf + 3 * 64 * 68;

    const int tid = threadIdx.x;
    const int tx = tid & 15;
    const int ty = tid >> 4;
    const int jt = blockIdx.x;
    const int h  = blockIdx.y;
    const int b  = blockIdx.z;
    const int q0 = jt * 64;

    const int lrow = tid >> 2;
    const int lcol = (tid & 3) << 2;

    {
        const float* qg = g_q + ((size_t)(b * Sv + q0 + lrow)) * Dv + h * 64;
        #pragma unroll
        for (int c0 = 0; c0 < 64; c0 += 16) {
            int col = c0 + lcol;
            float4 a = *(const float4*)(qg + col);
            Qt[(col + 0) * 68 + lrow] = a.x;
            Qt[(col + 1) * 68 + lrow] = a.y;
            Qt[(col + 2) * 68 + lrow] = a.z;
            Qt[(col + 3) * 68 + lrow] = a.w;
        }
    }

    float m[4], l[4], acc[4][4];
    #pragma unroll
    for (int i = 0; i < 4; ++i) {
        m[i] = -INFINITY; l[i] = 0.f;
        #pragma unroll
        for (int j = 0; j < 4; ++j) acc[i][j] = 0.f;
    }

    for (int j = 0; j <= jt; ++j) {
        __syncthreads();
        {
            const float* kg = g_k + (size_t)(b * Sv + j * 64 + lrow) * Dv + h * 64;
            const float* vg = g_v + (size_t)(b * Sv + j * 64 + lrow) * Dv + h * 64;
            #pragma unroll
            for (int c0 = 0; c0 < 64; c0 += 16) {
                int col = c0 + lcol;
                float4 kk = *(const float4*)(kg + col);
                Kt[(col + 0) * 68 + lrow] = kk.x;
                Kt[(col + 1) * 68 + lrow] = kk.y;
                Kt[(col + 2) * 68 + lrow] = kk.z;
                Kt[(col + 3) * 68 + lrow] = kk.w;
                float4 vv = *(const float4*)(vg + col);
                *(float4*)&Vs[lrow * 68 + col] = vv;
            }
        }
        __syncthreads();

        float sacc[4][4] = {};
        #pragma unroll 8
        for (int d = 0; d < 64; ++d) {
            float4 av = *(const float4*)&Qt[d * 68 + ty * 4];
            float4 bv = *(const float4*)&Kt[d * 68 + tx * 4];
            float ar[4] = {av.x, av.y, av.z, av.w};
            float br[4] = {bv.x, bv.y, bv.z, bv.w};
            #pragma unroll
            for (int i = 0; i < 4; ++i)
                #pragma unroll
                for (int jj = 0; jj < 4; ++jj)
                    sacc[i][jj] = fmaf(ar[i], br[jj], sacc[i][jj]);
        }

        if (j == jt) {
            #pragma unroll
            for (int i = 0; i < 4; ++i)
                #pragma unroll
                for (int jj = 0; jj < 4; ++jj)
                    if (tx * 4 + jj > ty * 4 + i) sacc[i][jj] = -INFINITY;
        }

        #pragma unroll
        for (int i = 0; i < 4; ++i) {
            float t = fmaxf(fmaxf(sacc[i][0], sacc[i][1]),
                            fmaxf(sacc[i][2], sacc[i][3]));
            #pragma unroll
            for (int o = 1; o < 16; o <<= 1)
                t = fmaxf(t, __shfl_xor_sync(0xffffffffu, t, o));
            float mnew = fmaxf(m[i], t);
            float scale = __expf(m[i] - mnew);
            float pr[4];
            float sum = 0.f;
            #pragma unroll
            for (int jj = 0; jj < 4; ++jj) {
                pr[jj] = __expf(sacc[i][jj] - mnew);
                sum += pr[jj];
            }
            *(float4*)&Ps[(ty * 4 + i) * 68 + tx * 4] =
                make_float4(pr[0], pr[1], pr[2], pr[3]);
            #pragma unroll
            for (int o = 1; o < 16; o <<= 1)
                sum += __shfl_xor_sync(0xffffffffu, sum, o);
            l[i] = l[i] * scale + sum;
            m[i] = mnew;
            #pragma unroll
            for (int jj = 0; jj < 4; ++jj) acc[i][jj] *= scale;
        }
        __syncthreads();

        #pragma unroll 8
        for (int c = 0; c < 64; ++c) {
            float4 bv = *(const float4*)&Vs[c * 68 + tx * 4];
            #pragma unroll
            for (int i = 0; i < 4; ++i) {
                float a = Ps[(ty * 4 + i) * 68 + c];
                acc[i][0] = fmaf(a, bv.x, acc[i][0]);
                acc[i][1] = fmaf(a, bv.y, acc[i][1]);
                acc[i][2] = fmaf(a, bv.z, acc[i][2]);
                acc[i][3] = fmaf(a, bv.w, acc[i][3]);
            }
        }
    }

    #pragma unroll
    for (int i = 0; i < 4; ++i) {
        float invl = 1.f / l[i];
        float4 o = make_float4(acc[i][0] * invl, acc[i][1] * invl,
                               acc[i][2] * invl, acc[i][3] * invl);
        *(float4*)&g_attn[(size_t)(b * Sv + q0 + ty * 4 + i) * Dv + h * 64 + tx * 4] = o;
    }
}

// ---------------------------------------------------------------------------
extern "C" void kernel_launch(void* const* d_in, const int* in_sizes, int n_in,
                              void* d_out, int out_size)
{
    const float* x  = (const float*)d_in[0];
    const int*   tp = (const int*)d_in[1];
    const float* w[4] = {(const float*)d_in[2], (const float*)d_in[3],
                         (const float*)d_in[4], (const float*)d_in[5]};
    float* out = (float*)d_out;

    float *pq, *pk, *pv, *pa;
    __nv_bfloat16 *pxs, *pas, *pws;
    cudaGetSymbolAddress((void**)&pq,  g_q);
    cudaGetSymbolAddress((void**)&pk,  g_k);
    cudaGetSymbolAddress((void**)&pv,  g_v);
    cudaGetSymbolAddress((void**)&pa,  g_attn);
    cudaGetSymbolAddress((void**)&pxs, g_xs);
    cudaGetSymbolAddress((void**)&pas, g_as);
    cudaGetSymbolAddress((void**)&pws, g_ws);

    const int gemm_smem = 65536 + 1024;
    cudaFuncSetAttribute(gemm_mma, cudaFuncAttributeMaxDynamicSharedMemorySize,
                         gemm_smem);
    const size_t attn_smem = 4 * 64 * 68 * sizeof(float);
    cudaFuncSetAttribute(attn_kernel, cudaFuncAttributeMaxDynamicSharedMemorySize,
                         (int)attn_smem);

    // 1) split conversions
    split_kernel<<<(Nv * Dv) / (4 * 256), 256>>>(x, pxs, Nv * Dv, 0);
    for (int i = 0; i < 4; ++i)
        split_kernel<<<(Dv * Dv) / (4 * 256), 256>>>(
            w[i], pws + (size_t)i * Dv * TKv, Dv * Dv, 1);

    // 2) projection GEMMs on mma.sync tensor cores
    dim3 gg(Dv / 128, Nv / 128);   // (8, 32)
    gemm_mma<<<gg, 256, gemm_smem>>>(pxs, pws + 0 * (size_t)Dv * TKv, pq, tp, 2);
    gemm_mma<<<gg, 256, gemm_smem>>>(pxs, pws + 1 * (size_t)Dv * TKv, pk, tp, 1);
    gemm_mma<<<gg, 256, gemm_smem>>>(pxs, pws + 2 * (size_t)Dv * TKv, pv, tp, 0);

    // 3) attention
    attn_kernel<<<dim3(Sv / 64, Hv, Bv), 256, attn_smem>>>();

    // 4) output projection
    split_kernel<<<(Nv * Dv) / (4 * 256), 256>>>(pa, pas, Nv * Dv, 0);
    gemm_mma<<<gg, 256, gemm_smem>>>(pas, pws + 3 * (size_t)Dv * TKv, out, tp, 0);
}

// round 5
// speedup vs baseline: 2.4994x; 1.6213x over previous
#include <cuda_runtime.h>
#include <cuda_bf16.h>
#include <math.h>
#include <stdint.h>

// Problem constants
#define Bv 2
#define Sv 2048
#define Dv 1024
#define Hv 16
#define DKv 64
#define Nv (Bv * Sv)     // 4096 rows
#define BHv (Bv * Hv)    // 32
#define TKv 3072         // split-bf16 concatenated K
#define SLABK 64
#define NSLAB (TKv / SLABK)  // 48

// ---------------------------------------------------------------------------
// Scratch (device globals — no cudaMalloc allowed)
// ---------------------------------------------------------------------------
__device__ float g_q[(size_t)Nv * Dv];
__device__ float g_k[(size_t)Nv * Dv];
__device__ float g_v[(size_t)Nv * Dv];
__device__ __nv_bfloat16 g_xs[(size_t)Nv * TKv];          // [Xhi|Xhi|Xlo]
__device__ __nv_bfloat16 g_as[(size_t)Nv * TKv];          // attn out split
__device__ __nv_bfloat16 g_ws[4][(size_t)Dv * TKv];       // [Whi|Wlo|Whi] x4
// attention operand layouts (bf16 hi/lo)
__device__ __nv_bfloat16 g_qh[(size_t)BHv * Sv * DKv];    // [bh][s][dk]
__device__ __nv_bfloat16 g_ql[(size_t)BHv * Sv * DKv];
__device__ __nv_bfloat16 g_kh[(size_t)BHv * Sv * DKv];
__device__ __nv_bfloat16 g_kl[(size_t)BHv * Sv * DKv];
__device__ __nv_bfloat16 g_vh[(size_t)BHv * DKv * Sv];    // [bh][dk][s]
__device__ __nv_bfloat16 g_vl[(size_t)BHv * DKv * Sv];

__device__ __forceinline__ uint32_t smem_to_u32(const void* p) {
    uint32_t a;
    asm("{ .reg .u64 t; cvta.to.shared.u64 t, %1; cvt.u32.u64 %0, t; }"
        : "=r"(a) : "l"(p));
    return a;
}
#define SW128(off) ((off) ^ (((off) >> 3) & 0x70))

__device__ __forceinline__ void ldm_x4(uint32_t* r, uint32_t addr) {
    asm volatile("ldmatrix.sync.aligned.m8n8.x4.shared.b16 {%0,%1,%2,%3}, [%4];"
        : "=r"(r[0]), "=r"(r[1]), "=r"(r[2]), "=r"(r[3]) : "r"(addr));
}
__device__ __forceinline__ void mma_16816(float* d, const uint32_t* a,
                                          const uint32_t* b) {
    asm volatile(
        "mma.sync.aligned.m16n8k16.row.col.f32.bf16.bf16.f32 "
        "{%0,%1,%2,%3}, {%4,%5,%6,%7}, {%8,%9}, {%0,%1,%2,%3};"
        : "+f"(d[0]), "+f"(d[1]), "+f"(d[2]), "+f"(d[3])
        : "r"(a[0]), "r"(a[1]), "r"(a[2]), "r"(a[3]), "r"(b[0]), "r"(b[1]));
}
__device__ __forceinline__ void cpa16(uint32_t dst, const void* src) {
    asm volatile("cp.async.cg.shared.global [%0], [%1], 16;"
        :: "r"(dst), "l"(src));
}
#define CP_COMMIT() asm volatile("cp.async.commit_group;" ::: "memory")
#define CP_WAIT(n)  asm volatile("cp.async.wait_group %0;" :: "n"(n) : "memory")

// ---------------------------------------------------------------------------
// Split fp32 -> [hi|hi|lo] (bmode=0) or [hi|lo|hi] (bmode=1)
// ---------------------------------------------------------------------------
__global__ __launch_bounds__(256) void split_kernel(
    const float* __restrict__ src, __nv_bfloat16* __restrict__ dst,
    int total, int bmode)
{
    int gid = blockIdx.x * blockDim.x + threadIdx.x;
    int e0 = gid * 4;
    if (e0 >= total) return;
    int r = e0 >> 10;
    int c = e0 & 1023;
    float4 v = *(const float4*)(src + e0);

    __nv_bfloat16 h0 = __float2bfloat16(v.x);
    __nv_bfloat16 h1 = __float2bfloat16(v.y);
    __nv_bfloat16 h2 = __float2bfloat16(v.z);
    __nv_bfloat16 h3 = __float2bfloat16(v.w);
    __nv_bfloat16 l0 = __float2bfloat16(v.x - __bfloat162float(h0));
    __nv_bfloat16 l1 = __float2bfloat16(v.y - __bfloat162float(h1));
    __nv_bfloat16 l2 = __float2bfloat16(v.z - __bfloat162float(h2));
    __nv_bfloat16 l3 = __float2bfloat16(v.w - __bfloat162float(h3));

    __nv_bfloat162 hp0 = {h0, h1}, hp1 = {h2, h3};
    __nv_bfloat162 lp0 = {l0, l1}, lp1 = {l2, l3};
    uint2 hu, lu;
    hu.x = *(uint32_t*)&hp0; hu.y = *(uint32_t*)&hp1;
    lu.x = *(uint32_t*)&lp0; lu.y = *(uint32_t*)&lp1;

    size_t base = (size_t)r * TKv + c;
    *(uint2*)(dst + base)        = hu;
    *(uint2*)(dst + base + 1024) = bmode ? lu : hu;
    *(uint2*)(dst + base + 2048) = bmode ? hu : lu;
}

// ---------------------------------------------------------------------------
// mma.sync bf16 projection GEMM (unchanged from R4, proven)
// ---------------------------------------------------------------------------
__global__ __launch_bounds__(256, 1) void gemm_mma(
    const __nv_bfloat16* __restrict__ A, const __nv_bfloat16* __restrict__ Bw,
    float* __restrict__ Y, const int* __restrict__ tp, int mode)
{
    extern __shared__ char smraw[];
    uint32_t smem_u = smem_to_u32(smraw);
    uint32_t base = (smem_u + 1023u) & ~1023u;
    char* sm = smraw + (base - smem_u);

    const int tid = threadIdx.x;
    const int wid = tid >> 5;
    const int lane = tid & 31;
    const int wm = wid >> 1;
    const int wn = wid & 1;
    const int m0 = blockIdx.y * 128;
    const int e0 = blockIdx.x * 128;
    const int g2 = lane >> 2;
    const int t4 = lane & 3;

    const __nv_bfloat16* Ag = A + (size_t)m0 * TKv;
    const __nv_bfloat16* Bg = Bw + (size_t)e0 * TKv;

    float acc[2][8][4];
    #pragma unroll
    for (int i = 0; i < 2; ++i)
        #pragma unroll
        for (int j = 0; j < 8; ++j)
            #pragma unroll
            for (int k = 0; k < 4; ++k) acc[i][j][k] = 0.f;

    const int lrow = lane & 15;
    const int lkoff = ((lane >> 4) & 1) * 16;

    {
        #pragma unroll
        for (int kk = 0; kk < 4; ++kk) {
            int idx = kk * 256 + tid;
            int r = idx >> 3, c = idx & 7;
            size_t goff = (size_t)r * TKv + c * 8;
            uint32_t so = SW128((uint32_t)(r * 128 + c * 16));
            *(uint4*)(sm + so)         = *(const uint4*)(Ag + goff);
            *(uint4*)(sm + 16384 + so) = *(const uint4*)(Bg + goff);
        }
    }
    __syncthreads();

    for (int s = 0; s < NSLAB; ++s) {
        const int cur = s & 1;
        char* pA = sm + cur * 32768;
        char* pB = sm + cur * 32768 + 16384;

        uint4 pa[4], pb[4];
        if (s + 1 < NSLAB) {
            #pragma unroll
            for (int kk = 0; kk < 4; ++kk) {
                int idx = kk * 256 + tid;
                int r = idx >> 3, c = idx & 7;
                size_t goff = (size_t)r * TKv + (s + 1) * SLABK + c * 8;
                pa[kk] = *(const uint4*)(Ag + goff);
                pb[kk] = *(const uint4*)(Bg + goff);
            }
        }

        const uint32_t pAu = smem_to_u32(pA);
        const uint32_t pBu = smem_to_u32(pB);
        #pragma unroll
        for (int ks = 0; ks < 4; ++ks) {
            const uint32_t kbyte = ks * 32 + lkoff;
            uint32_t afr[2][4], bfr[4][4];
            #pragma unroll
            for (int am = 0; am < 2; ++am) {
                uint32_t off = (uint32_t)((wm * 32 + am * 16 + lrow) * 128) + kbyte;
                ldm_x4(afr[am], pAu + SW128(off));
            }
            #pragma unroll
            for (int bn = 0; bn < 4; ++bn) {
                uint32_t off = (uint32_t)((wn * 64 + bn * 16 + lrow) * 128) + kbyte;
                ldm_x4(bfr[bn], pBu + SW128(off));
            }
            #pragma unroll
            for (int am = 0; am < 2; ++am)
                #pragma unroll
                for (int bn = 0; bn < 4; ++bn) {
                    uint32_t blo[2] = {bfr[bn][0], bfr[bn][2]};
                    uint32_t bhi[2] = {bfr[bn][1], bfr[bn][3]};
                    mma_16816(acc[am][bn * 2],     afr[am], blo);
                    mma_16816(acc[am][bn * 2 + 1], afr[am], bhi);
                }
        }
        __syncthreads();

        if (s + 1 < NSLAB) {
            char* nA = sm + ((s + 1) & 1) * 32768;
            char* nB = nA + 16384;
            #pragma unroll
            for (int kk = 0; kk < 4; ++kk) {
                int idx = kk * 256 + tid;
                int r = idx >> 3, c = idx & 7;
                uint32_t so = SW128((uint32_t)(r * 128 + c * 16));
                *(uint4*)(nA + so) = pa[kk];
                *(uint4*)(nB + so) = pb[kk];
            }
            __syncthreads();
        }
    }

    const float qs = (mode == 2) ? 0.125f : 1.0f;
    const float LTH = 0.2878231366242557f;
    #pragma unroll
    for (int am = 0; am < 2; ++am) {
        #pragma unroll
        for (int half = 0; half < 2; ++half) {
            int m = m0 + wm * 32 + am * 16 + g2 + half * 8;
            float* yr = Y + (size_t)m * Dv;
            float pos = (mode != 0) ? (float)tp[m & (Sv - 1)] : 0.f;
            #pragma unroll
            for (int bn = 0; bn < 8; ++bn) {
                int e = e0 + wn * 64 + bn * 8 + t4 * 2;
                float d0 = acc[am][bn][half * 2];
                float d1 = acc[am][bn][half * 2 + 1];
                if (mode != 0) {
                    int p = (e & (DKv - 1)) >> 1;
                    float inv = expf(-LTH * (float)p);
                    float sn, cs;
                    sincosf(pos * inv, &sn, &cs);
                    float o0 = (cs * d0 - sn * d1) * qs;
                    float o1 = (sn * d0 + cs * d1) * qs;
                    d0 = o0; d1 = o1;
                }
                *(float2*)(yr + e) = make_float2(d0, d1);
            }
        }
    }
}

// ---------------------------------------------------------------------------
// Prep: fp32 Q/K [n][1024] -> bf16 hi/lo [bh][s][64]
// ---------------------------------------------------------------------------
__global__ __launch_bounds__(256) void qk_prep(
    const float* __restrict__ src, __nv_bfloat16* __restrict__ dh,
    __nv_bfloat16* __restrict__ dl)
{
    size_t L = ((size_t)blockIdx.x * 256 + threadIdx.x) * 8;   // dest linear
    int bh = (int)(L >> 17);              // / (2048*64)
    int rem = (int)(L & 131071);
    int s = rem >> 6;
    int dk = rem & 63;
    int b = bh >> 4, h = bh & 15;
    size_t sidx = ((size_t)(b * Sv + s)) * Dv + h * 64 + dk;
    float4 v0 = *(const float4*)(src + sidx);
    float4 v1 = *(const float4*)(src + sidx + 4);

    float vv[8] = {v0.x, v0.y, v0.z, v0.w, v1.x, v1.y, v1.z, v1.w};
    uint32_t hu[4], lu[4];
    #pragma unroll
    for (int i = 0; i < 4; ++i) {
        __nv_bfloat162 hp = __floats2bfloat162_rn(vv[2*i], vv[2*i+1]);
        float r0 = __bfloat162float(hp.x), r1 = __bfloat162float(hp.y);
        __nv_bfloat162 lp = __floats2bfloat162_rn(vv[2*i] - r0, vv[2*i+1] - r1);
        hu[i] = *(uint32_t*)&hp;
        lu[i] = *(uint32_t*)&lp;
    }
    *(uint4*)(dh + L) = make_uint4(hu[0], hu[1], hu[2], hu[3]);
    *(uint4*)(dl + L) = make_uint4(lu[0], lu[1], lu[2], lu[3]);
}

// ---------------------------------------------------------------------------
// Prep: fp32 V [n][1024] -> bf16 hi/lo transposed [bh][dk][s]
// grid (S/64, BH), block 256
// ---------------------------------------------------------------------------
__global__ __launch_bounds__(256) void v_prep()
{
    __shared__ float sv[64][65];
    const int tid = threadIdx.x;
    const int st = blockIdx.x, bh = blockIdx.y;
    const int s0 = st * 64;
    const int b = bh >> 4, h = bh & 15;

    #pragma unroll
    for (int p = 0; p < 4; ++p) {
        int idx = p * 256 + tid;         // 0..1023 float4s
        int r = idx >> 4, c = (idx & 15) * 4;
        float4 v = *(const float4*)(g_v + ((size_t)(b * Sv + s0 + r)) * Dv + h * 64 + c);
        sv[r][c] = v.x; sv[r][c+1] = v.y; sv[r][c+2] = v.z; sv[r][c+3] = v.w;
    }
    __syncthreads();

    int dk = tid >> 2;
    int t0 = (tid & 3) * 16;
    uint32_t hu[8], lu[8];
    #pragma unroll
    for (int i = 0; i < 8; ++i) {
        float a = sv[t0 + 2*i][dk], c = sv[t0 + 2*i + 1][dk];
        __nv_bfloat162 hp = __floats2bfloat162_rn(a, c);
        float r0 = __bfloat162float(hp.x), r1 = __bfloat162float(hp.y);
        __nv_bfloat162 lp = __floats2bfloat162_rn(a - r0, c - r1);
        hu[i] = *(uint32_t*)&hp;
        lu[i] = *(uint32_t*)&lp;
    }
    size_t o = ((size_t)bh * 64 + dk) * Sv + s0 + t0;
    *(uint4*)(g_vh + o)     = make_uint4(hu[0], hu[1], hu[2], hu[3]);
    *(uint4*)(g_vh + o + 8) = make_uint4(hu[4], hu[5], hu[6], hu[7]);
    *(uint4*)(g_vl + o)     = make_uint4(lu[0], lu[1], lu[2], lu[3]);
    *(uint4*)(g_vl + o + 8) = make_uint4(lu[4], lu[5], lu[6], lu[7]);
}

// ---------------------------------------------------------------------------
// Flash attention on mma.sync with 3-term split-bf16 for S=QK^T and O=PV.
// CTA: 128 q rows x one (b,h). 8 warps x 16 rows. kv tiles of 64, cp.async 2-buf.
// Writes output directly as split bf16 [hi|hi|lo] into g_as.
// ---------------------------------------------------------------------------
__device__ __forceinline__ void qk_term(
    float (&sacc)[8][4], uint32_t aBase, uint32_t bBase,
    int wid, int lrow, int lkoff)
{
    #pragma unroll
    for (int ks = 0; ks < 4; ++ks) {
        uint32_t kbyte = (uint32_t)(ks * 32 + lkoff);
        uint32_t afr[4];
        ldm_x4(afr, aBase + SW128((uint32_t)((wid * 16 + lrow) * 128) + kbyte));
        #pragma unroll
        for (int bn4 = 0; bn4 < 4; ++bn4) {
            uint32_t bfr[4];
            ldm_x4(bfr, bBase + SW128((uint32_t)((bn4 * 16 + lrow) * 128) + kbyte));
            uint32_t blo[2] = {bfr[0], bfr[2]};
            uint32_t bhi[2] = {bfr[1], bfr[3]};
            mma_16816(sacc[2 * bn4],     afr, blo);
            mma_16816(sacc[2 * bn4 + 1], afr, bhi);
        }
    }
}

__device__ __forceinline__ void attn_load_tile(
    uint32_t sb, uint32_t oKh, uint32_t oKl, uint32_t oVh, uint32_t oVl,
    int bh, int j, int buf, int tid)
{
    const char* kh = (const char*)(g_kh + ((size_t)bh * Sv + j * 64) * 64);
    const char* kl = (const char*)(g_kl + ((size_t)bh * Sv + j * 64) * 64);
    #pragma unroll
    for (int p = 0; p < 2; ++p) {
        int idx = p * 256 + tid;      // 0..511
        int r = idx >> 3, c = idx & 7;
        uint32_t so = SW128((uint32_t)(r * 128 + c * 16));
        uint32_t bo = (uint32_t)(buf * 8192);
        cpa16(sb + oKh + bo + so, kh + idx * 16);
        cpa16(sb + oKl + bo + so, kl + idx * 16);
        const char* vh = (const char*)(g_vh + ((size_t)bh * 64 + r) * Sv + j * 64);
        const char* vl = (const char*)(g_vl + ((size_t)bh * 64 + r) * Sv + j * 64);
        cpa16(sb + oVh + bo + so, vh + c * 16);
        cpa16(sb + oVl + bo + so, vl + c * 16);
    }
}

__global__ __launch_bounds__(256, 1) void attn_mma()
{
    extern __shared__ char smraw[];
    uint32_t su = smem_to_u32(smraw);
    uint32_t sb = (su + 1023u) & ~1023u;
    const uint32_t oQh = 0, oQl = 16384;
    const uint32_t oKh = 32768, oKl = 49152;   // 2 bufs x 8KB each
    const uint32_t oVh = 65536, oVl = 81920;

    const int tid = threadIdx.x;
    const int wid = tid >> 5, lane = tid & 31;
    const int g2 = lane >> 2, t4 = lane & 3;
    const int lrow = lane & 15;
    const int lkoff = ((lane >> 4) & 1) * 16;

    const int qt = gridDim.x - 1 - blockIdx.x;   // big tiles first
    const int h = blockIdx.y, b = blockIdx.z;
    const int bh = b * Hv + h;
    const int q0 = qt * 128;
    const int jmax = 2 * qt + 1;

    // prologue: Q (hi+lo) + tile 0, one commit group
    {
        const char* qh = (const char*)(g_qh + ((size_t)bh * Sv + q0) * 64);
        const char* ql = (const char*)(g_ql + ((size_t)bh * Sv + q0) * 64);
        #pragma unroll
        for (int p = 0; p < 4; ++p) {
            int idx = p * 256 + tid;     // 0..1023
            uint32_t so = SW128((uint32_t)(idx * 16));
            cpa16(sb + oQh + so, qh + idx * 16);
            cpa16(sb + oQl + so, ql + idx * 16);
        }
        attn_load_tile(sb, oKh, oKl, oVh, oVl, bh, 0, 0, tid);
        CP_COMMIT();
    }

    float m0 = -1e30f, m1 = -1e30f, l0 = 0.f, l1 = 0.f;
    float oacc[8][4];
    #pragma unroll
    for (int i = 0; i < 8; ++i)
        #pragma unroll
        for (int c = 0; c < 4; ++c) oacc[i][c] = 0.f;

    for (int j = 0; j <= jmax; ++j) {
        const int cur = j & 1;
        if (j < jmax) {
            attn_load_tile(sb, oKh, oKl, oVh, oVl, bh, j + 1, cur ^ 1, tid);
            CP_COMMIT();
            CP_WAIT(1);
        } else {
            CP_WAIT(0);
        }
        __syncthreads();

        // S = Qhi*Khi + Qhi*Klo + Qlo*Khi
        float sacc[8][4];
        #pragma unroll
        for (int i = 0; i < 8; ++i)
            #pragma unroll
            for (int c = 0; c < 4; ++c) sacc[i][c] = 0.f;
        {
            uint32_t kb = (uint32_t)(cur * 8192);
            qk_term(sacc, sb + oQh, sb + oKh + kb, wid, lrow, lkoff);
            qk_term(sacc, sb + oQh, sb + oKl + kb, wid, lrow, lkoff);
            qk_term(sacc, sb + oQl, sb + oKh + kb, wid, lrow, lkoff);
        }

        // causal mask (only the two diagonal-adjacent tiles)
        if (j >= 2 * qt) {
            int r0 = q0 + wid * 16 + g2;
            #pragma unroll
            for (int bn = 0; bn < 8; ++bn) {
                int col = j * 64 + bn * 8 + 2 * t4;
                #pragma unroll
                for (int c = 0; c < 4; ++c) {
                    int row = r0 + ((c >= 2) ? 8 : 0);
                    if (col + (c & 1) > row) sacc[bn][c] = -1e30f;
                }
            }
        }

        // online softmax (rows g2 and g2+8, reduce over t4 lanes)
        float tm0 = -1e30f, tm1 = -1e30f;
        #pragma unroll
        for (int bn = 0; bn < 8; ++bn) {
            tm0 = fmaxf(tm0, fmaxf(sacc[bn][0], sacc[bn][1]));
            tm1 = fmaxf(tm1, fmaxf(sacc[bn][2], sacc[bn][3]));
        }
        tm0 = fmaxf(tm0, __shfl_xor_sync(0xffffffffu, tm0, 1));
        tm0 = fmaxf(tm0, __shfl_xor_sync(0xffffffffu, tm0, 2));
        tm1 = fmaxf(tm1, __shfl_xor_sync(0xffffffffu, tm1, 1));
        tm1 = fmaxf(tm1, __shfl_xor_sync(0xffffffffu, tm1, 2));
        float mn0 = fmaxf(m0, tm0), mn1 = fmaxf(m1, tm1);
        float sc0 = __expf(m0 - mn0), sc1 = __expf(m1 - mn1);
        float rs0 = 0.f, rs1 = 0.f;
        #pragma unroll
        for (int bn = 0; bn < 8; ++bn) {
            sacc[bn][0] = __expf(sacc[bn][0] - mn0);
            sacc[bn][1] = __expf(sacc[bn][1] - mn0);
            sacc[bn][2] = __expf(sacc[bn][2] - mn1);
            sacc[bn][3] = __expf(sacc[bn][3] - mn1);
            rs0 += sacc[bn][0] + sacc[bn][1];
            rs1 += sacc[bn][2] + sacc[bn][3];
        }
        rs0 += __shfl_xor_sync(0xffffffffu, rs0, 1);
        rs0 += __shfl_xor_sync(0xffffffffu, rs0, 2);
        rs1 += __shfl_xor_sync(0xffffffffu, rs1, 1);
        rs1 += __shfl_xor_sync(0xffffffffu, rs1, 2);
        l0 = l0 * sc0 + rs0;
        l1 = l1 * sc1 + rs1;
        m0 = mn0; m1 = mn1;
        #pragma unroll
        for (int bn = 0; bn < 8; ++bn) {
            oacc[bn][0] *= sc0; oacc[bn][1] *= sc0;
            oacc[bn][2] *= sc1; oacc[bn][3] *= sc1;
        }

        // O += Phi*Vhi + Phi*Vlo + Plo*Vhi
        {
            uint32_t vhB = sb + oVh + (uint32_t)(cur * 8192);
            uint32_t vlB = sb + oVl + (uint32_t)(cur * 8192);
            #pragma unroll
            for (int ks = 0; ks < 4; ++ks) {
                uint32_t ah[4], al[4];
                #pragma unroll
                for (int q = 0; q < 4; ++q) {
                    int tl = 2 * ks + (q >> 1);
                    int c0 = (q & 1) * 2;
                    float a = sacc[tl][c0], c = sacc[tl][c0 + 1];
                    __nv_bfloat162 hp = __floats2bfloat162_rn(a, c);
                    float r0 = __bfloat162float(hp.x), r1 = __bfloat162float(hp.y);
                    __nv_bfloat162 lp = __floats2bfloat162_rn(a - r0, c - r1);
                    ah[q] = *(uint32_t*)&hp;
                    al[q] = *(uint32_t*)&lp;
                }
                // reorder: a-frag = {t=2ks c01, t=2ks c23, t=2ks+1 c01, t=2ks+1 c23}
                uint32_t ahf[4] = {ah[0], ah[1], ah[2], ah[3]};
                uint32_t alf[4] = {al[0], al[1], al[2], al[3]};
                uint32_t kbyte = (uint32_t)(ks * 32 + lkoff);
                #pragma unroll
                for (int bn4 = 0; bn4 < 4; ++bn4) {
                    uint32_t bH[4], bL[4];
                    uint32_t off = SW128((uint32_t)((bn4 * 16 + lrow) * 128) + kbyte);
                    ldm_x4(bH, vhB + off);
                    ldm_x4(bL, vlB + off);
                    uint32_t bHl[2] = {bH[0], bH[2]}, bHh[2] = {bH[1], bH[3]};
                    uint32_t bLl[2] = {bL[0], bL[2]}, bLh[2] = {bL[1], bL[3]};
                    mma_16816(oacc[2 * bn4],     ahf, bHl);
                    mma_16816(oacc[2 * bn4 + 1], ahf, bHh);
                    mma_16816(oacc[2 * bn4],     ahf, bLl);
                    mma_16816(oacc[2 * bn4 + 1], ahf, bLh);
                    mma_16816(oacc[2 * bn4],     alf, bHl);
                    mma_16816(oacc[2 * bn4 + 1], alf, bHh);
                }
            }
        }
        __syncthreads();
    }

    // epilogue: normalize, write split bf16 [hi|hi|lo] rows of g_as
    float il0 = 1.f / l0, il1 = 1.f / l1;
    int row0 = q0 + wid * 16 + g2;
    size_t n0 = (size_t)b * Sv + row0;
    #pragma unroll
    for (int bn = 0; bn < 8; ++bn) {
        int col = h * 64 + bn * 8 + 2 * t4;
        #pragma unroll
        for (int half = 0; half < 2; ++half) {
            float v0 = oacc[bn][half * 2]     * (half ? il1 : il0);
            float v1 = oacc[bn][half * 2 + 1] * (half ? il1 : il0);
            __nv_bfloat162 hp = __floats2bfloat162_rn(v0, v1);
            float r0 = __bfloat162float(hp.x), r1 = __bfloat162float(hp.y);
            __nv_bfloat162 lp = __floats2bfloat162_rn(v0 - r0, v1 - r1);
            size_t base = (n0 + half * 8) * TKv + col;
            *(uint32_t*)(g_as + base)        = *(uint32_t*)&hp;
            *(uint32_t*)(g_as + base + 1024) = *(uint32_t*)&hp;
            *(uint32_t*)(g_as + base + 2048) = *(uint32_t*)&lp;
        }
    }
}

// ---------------------------------------------------------------------------
extern "C" void kernel_launch(void* const* d_in, const int* in_sizes, int n_in,
                              void* d_out, int out_size)
{
    const float* x  = (const float*)d_in[0];
    const int*   tp = (const int*)d_in[1];
    const float* w[4] = {(const float*)d_in[2], (const float*)d_in[3],
                         (const float*)d_in[4], (const float*)d_in[5]};
    float* out = (float*)d_out;

    float *pq, *pk, *pv;
    __nv_bfloat16 *pxs, *pas, *pws, *pqh, *pql, *pkh, *pkl;
    cudaGetSymbolAddress((void**)&pq,  g_q);
    cudaGetSymbolAddress((void**)&pk,  g_k);
    cudaGetSymbolAddress((void**)&pv,  g_v);
    cudaGetSymbolAddress((void**)&pxs, g_xs);
    cudaGetSymbolAddress((void**)&pas, g_as);
    cudaGetSymbolAddress((void**)&pws, g_ws);
    cudaGetSymbolAddress((void**)&pqh, g_qh);
    cudaGetSymbolAddress((void**)&pql, g_ql);
    cudaGetSymbolAddress((void**)&pkh, g_kh);
    cudaGetSymbolAddress((void**)&pkl, g_kl);

    const int gemm_smem = 65536 + 1024;
    cudaFuncSetAttribute(gemm_mma, cudaFuncAttributeMaxDynamicSharedMemorySize,
                         gemm_smem);
    const int attn_smem = 96 * 1024 + 1024;
    cudaFuncSetAttribute(attn_mma, cudaFuncAttributeMaxDynamicSharedMemorySize,
                         attn_smem);

    // 1) split conversions
    split_kernel<<<(Nv * Dv) / (4 * 256), 256>>>(x, pxs, Nv * Dv, 0);
    for (int i = 0; i < 4; ++i)
        split_kernel<<<(Dv * Dv) / (4 * 256), 256>>>(
            w[i], pws + (size_t)i * Dv * TKv, Dv * Dv, 1);

    // 2) projection GEMMs
    dim3 gg(Dv / 128, Nv / 128);
    gemm_mma<<<gg, 256, gemm_smem>>>(pxs, pws + 0 * (size_t)Dv * TKv, pq, tp, 2);
    gemm_mma<<<gg, 256, gemm_smem>>>(pxs, pws + 1 * (size_t)Dv * TKv, pk, tp, 1);
    gemm_mma<<<gg, 256, gemm_smem>>>(pxs, pws + 2 * (size_t)Dv * TKv, pv, tp, 0);

    // 3) operand prep for tensor-core attention
    qk_prep<<<2048, 256>>>(pq, pqh, pql);
    qk_prep<<<2048, 256>>>(pk, pkh, pkl);
    v_prep<<<dim3(Sv / 64, BHv), 256>>>();

    // 4) attention (writes split bf16 g_as directly)
    attn_mma<<<dim3(Sv / 128, Hv, Bv), 256, attn_smem>>>();

    // 5) output projection
    gemm_mma<<<gg, 256, gemm_smem>>>(pas, pws + 3 * (size_t)Dv * TKv, out, tp, 0);
}

// round 6
// speedup vs baseline: 2.9664x; 1.1869x over previous
#include <cuda_runtime.h>
#include <cuda_bf16.h>
#include <math.h>
#include <stdint.h>

// Problem constants
#define Bv 2
#define Sv 2048
#define Dv 1024
#define Hv 16
#define DKv 64
#define Nv (Bv * Sv)     // 4096 rows
#define BHv (Bv * Hv)    // 32
#define TKv 3072         // split-bf16 concatenated K
#define SLABK 64
#define NSLAB (TKv / SLABK)  // 48

// ---------------------------------------------------------------------------
// Scratch (device globals — no cudaMalloc allowed)
// ---------------------------------------------------------------------------
__device__ float g_q[(size_t)Nv * Dv];
__device__ float g_k[(size_t)Nv * Dv];
__device__ float g_v[(size_t)Nv * Dv];
__device__ __nv_bfloat16 g_xs[(size_t)Nv * TKv];          // [Xhi|Xhi|Xlo]
__device__ __nv_bfloat16 g_as[(size_t)Nv * TKv];          // attn out split
__device__ __nv_bfloat16 g_ws[4][(size_t)Dv * TKv];       // [Whi|Wlo|Whi] x4
__device__ __nv_bfloat16 g_qh[(size_t)BHv * Sv * DKv];    // [bh][s][dk]
__device__ __nv_bfloat16 g_ql[(size_t)BHv * Sv * DKv];
__device__ __nv_bfloat16 g_kh[(size_t)BHv * Sv * DKv];
__device__ __nv_bfloat16 g_kl[(size_t)BHv * Sv * DKv];
__device__ __nv_bfloat16 g_vh[(size_t)BHv * DKv * Sv];    // [bh][dk][s]
__device__ __nv_bfloat16 g_vl[(size_t)BHv * DKv * Sv];

__device__ __forceinline__ uint32_t smem_to_u32(const void* p) {
    uint32_t a;
    asm("{ .reg .u64 t; cvta.to.shared.u64 t, %1; cvt.u32.u64 %0, t; }"
        : "=r"(a) : "l"(p));
    return a;
}
#define SW128(off) ((off) ^ (((off) >> 3) & 0x70))

__device__ __forceinline__ void ldm_x4(uint32_t* r, uint32_t addr) {
    asm volatile("ldmatrix.sync.aligned.m8n8.x4.shared.b16 {%0,%1,%2,%3}, [%4];"
        : "=r"(r[0]), "=r"(r[1]), "=r"(r[2]), "=r"(r[3]) : "r"(addr));
}
__device__ __forceinline__ void mma_16816(float* d, const uint32_t* a,
                                          const uint32_t* b) {
    asm volatile(
        "mma.sync.aligned.m16n8k16.row.col.f32.bf16.bf16.f32 "
        "{%0,%1,%2,%3}, {%4,%5,%6,%7}, {%8,%9}, {%0,%1,%2,%3};"
        : "+f"(d[0]), "+f"(d[1]), "+f"(d[2]), "+f"(d[3])
        : "r"(a[0]), "r"(a[1]), "r"(a[2]), "r"(a[3]), "r"(b[0]), "r"(b[1]));
}
__device__ __forceinline__ void cpa16(uint32_t dst, const void* src) {
    asm volatile("cp.async.cg.shared.global [%0], [%1], 16;"
        :: "r"(dst), "l"(src));
}
#define CP_COMMIT() asm volatile("cp.async.commit_group;" ::: "memory")
#define CP_WAIT(n)  asm volatile("cp.async.wait_group %0;" :: "n"(n) : "memory")

// ---------------------------------------------------------------------------
// Split fp32 x -> [hi|hi|lo] bf16
// ---------------------------------------------------------------------------
__device__ __forceinline__ void split_body(
    const float* __restrict__ src, __nv_bfloat16* __restrict__ dst,
    size_t e0, int bmode)
{
    int r = (int)(e0 >> 10);
    int c = (int)(e0 & 1023);
    float4 v = *(const float4*)(src + e0);

    float vv[4] = {v.x, v.y, v.z, v.w};
    uint2 hu, lu;
    {
        __nv_bfloat162 hp0 = __floats2bfloat162_rn(vv[0], vv[1]);
        __nv_bfloat162 hp1 = __floats2bfloat162_rn(vv[2], vv[3]);
        __nv_bfloat162 lp0 = __floats2bfloat162_rn(
            vv[0] - __bfloat162float(hp0.x), vv[1] - __bfloat162float(hp0.y));
        __nv_bfloat162 lp1 = __floats2bfloat162_rn(
            vv[2] - __bfloat162float(hp1.x), vv[3] - __bfloat162float(hp1.y));
        hu.x = *(uint32_t*)&hp0; hu.y = *(uint32_t*)&hp1;
        lu.x = *(uint32_t*)&lp0; lu.y = *(uint32_t*)&lp1;
    }
    size_t base = (size_t)r * TKv + c;
    *(uint2*)(dst + base)        = hu;
    *(uint2*)(dst + base + 1024) = bmode ? lu : hu;
    *(uint2*)(dst + base + 2048) = bmode ? hu : lu;
}

__global__ __launch_bounds__(256) void xsplit_kernel(const float* __restrict__ x)
{
    size_t e0 = ((size_t)blockIdx.x * 256 + threadIdx.x) * 4;
    split_body(x, g_xs, e0, 0);
}

// 4 weight matrices in one launch: grid = 4 * 1024 blocks
__global__ __launch_bounds__(256) void wsplit_kernel(
    const float* __restrict__ w0, const float* __restrict__ w1,
    const float* __restrict__ w2, const float* __restrict__ w3)
{
    int i = blockIdx.x >> 10;
    const float* src = (i == 0) ? w0 : (i == 1) ? w1 : (i == 2) ? w2 : w3;
    size_t e0 = ((size_t)(blockIdx.x & 1023) * 256 + threadIdx.x) * 4;
    split_body(src, g_ws[i], e0, 1);
}

// ---------------------------------------------------------------------------
// Shared GEMM tile body: 128x128 CTA tile, K'=3072, cp.async double buffer.
// mode: 0 plain, 1 RoPE (K), 2 RoPE + 1/8 (Q)
// ---------------------------------------------------------------------------
__device__ __forceinline__ void gemm_tile(
    const __nv_bfloat16* __restrict__ Ag, const __nv_bfloat16* __restrict__ Bg,
    float* __restrict__ Y, const int* __restrict__ tp, int mode,
    int m0, int e0, char* sm, uint32_t sbu)
{
    const int tid = threadIdx.x;
    const int wid = tid >> 5;
    const int lane = tid & 31;
    const int wm = wid >> 1;
    const int wn = wid & 1;
    const int g2 = lane >> 2;
    const int t4 = lane & 3;
    const int lrow = lane & 15;
    const int lkoff = ((lane >> 4) & 1) * 16;

    float acc[2][8][4];
    #pragma unroll
    for (int i = 0; i < 2; ++i)
        #pragma unroll
        for (int j = 0; j < 8; ++j)
            #pragma unroll
            for (int k = 0; k < 4; ++k) acc[i][j][k] = 0.f;

    // loader mapping: idx -> (row r, 16B chunk c)
    // prologue: slab 0 -> buffer 0
    {
        #pragma unroll
        for (int kk = 0; kk < 4; ++kk) {
            int idx = kk * 256 + tid;
            int r = idx >> 3, c = idx & 7;
            size_t goff = (size_t)r * TKv + c * 8;
            uint32_t so = SW128((uint32_t)(r * 128 + c * 16));
            cpa16(sbu + so,         Ag + goff);
            cpa16(sbu + 16384 + so, Bg + goff);
        }
        CP_COMMIT();
    }

    for (int s = 0; s < NSLAB; ++s) {
        const int cur = s & 1;
        if (s + 1 < NSLAB) {
            uint32_t nb = (uint32_t)(((s + 1) & 1) * 32768);
            #pragma unroll
            for (int kk = 0; kk < 4; ++kk) {
                int idx = kk * 256 + tid;
                int r = idx >> 3, c = idx & 7;
                size_t goff = (size_t)r * TKv + (s + 1) * SLABK + c * 8;
                uint32_t so = SW128((uint32_t)(r * 128 + c * 16));
                cpa16(sbu + nb + so,         Ag + goff);
                cpa16(sbu + nb + 16384 + so, Bg + goff);
            }
            CP_COMMIT();
            CP_WAIT(1);
        } else {
            CP_WAIT(0);
        }
        __syncthreads();

        const uint32_t pAu = sbu + (uint32_t)(cur * 32768);
        const uint32_t pBu = pAu + 16384;
        #pragma unroll
        for (int ks = 0; ks < 4; ++ks) {
            const uint32_t kbyte = (uint32_t)(ks * 32 + lkoff);
            uint32_t afr[2][4], bfr[4][4];
            #pragma unroll
            for (int am = 0; am < 2; ++am) {
                uint32_t off = (uint32_t)((wm * 32 + am * 16 + lrow) * 128) + kbyte;
                ldm_x4(afr[am], pAu + SW128(off));
            }
            #pragma unroll
            for (int bn = 0; bn < 4; ++bn) {
                uint32_t off = (uint32_t)((wn * 64 + bn * 16 + lrow) * 128) + kbyte;
                ldm_x4(bfr[bn], pBu + SW128(off));
            }
            #pragma unroll
            for (int am = 0; am < 2; ++am)
                #pragma unroll
                for (int bn = 0; bn < 4; ++bn) {
                    uint32_t blo[2] = {bfr[bn][0], bfr[bn][2]};
                    uint32_t bhi[2] = {bfr[bn][1], bfr[bn][3]};
                    mma_16816(acc[am][bn * 2],     afr[am], blo);
                    mma_16816(acc[am][bn * 2 + 1], afr[am], bhi);
                }
        }
        __syncthreads();
    }

    const float qs = (mode == 2) ? 0.125f : 1.0f;
    const float LTH = 0.2878231366242557f;   // ln(10000)/32
    #pragma unroll
    for (int am = 0; am < 2; ++am) {
        #pragma unroll
        for (int half = 0; half < 2; ++half) {
            int m = m0 + wm * 32 + am * 16 + g2 + half * 8;
            float* yr = Y + (size_t)m * Dv;
            float pos = (mode != 0) ? (float)tp[m & (Sv - 1)] : 0.f;
            #pragma unroll
            for (int bn = 0; bn < 8; ++bn) {
                int e = e0 + wn * 64 + bn * 8 + t4 * 2;
                float d0 = acc[am][bn][half * 2];
                float d1 = acc[am][bn][half * 2 + 1];
                if (mode != 0) {
                    int p = (e & (DKv - 1)) >> 1;
                    float inv = expf(-LTH * (float)p);
                    float sn, cs;
                    sincosf(pos * inv, &sn, &cs);
                    float o0 = (cs * d0 - sn * d1) * qs;
                    float o1 = (sn * d0 + cs * d1) * qs;
                    d0 = o0; d1 = o1;
                }
                *(float2*)(yr + e) = make_float2(d0, d1);
            }
        }
    }
}

// Fused QKV projection: grid (24, 32). Region by blockIdx.x >> 3.
__global__ __launch_bounds__(256, 2) void gemm_qkv(
    const int* __restrict__ tp, float* __restrict__ pq,
    float* __restrict__ pk, float* __restrict__ pv)
{
    extern __shared__ char smraw[];
    uint32_t su = smem_to_u32(smraw);
    uint32_t sbu = (su + 1023u) & ~1023u;
    char* sm = smraw + (sbu - su);

    const int region = blockIdx.x >> 3;          // 0=Q,1=K,2=V
    const int e0 = (blockIdx.x & 7) * 128;
    const int m0 = blockIdx.y * 128;
    const __nv_bfloat16* Ag = g_xs + (size_t)m0 * TKv;
    const __nv_bfloat16* Bg = g_ws[region] + (size_t)e0 * TKv;
    float* Y = (region == 0) ? pq : (region == 1) ? pk : pv;
    const int mode = (region == 0) ? 2 : (region == 1) ? 1 : 0;
    gemm_tile(Ag, Bg, Y, tp, mode, m0, e0, sm, sbu);
}

// Output projection: grid (8, 32)
__global__ __launch_bounds__(256, 2) void gemm_o(float* __restrict__ out)
{
    extern __shared__ char smraw[];
    uint32_t su = smem_to_u32(smraw);
    uint32_t sbu = (su + 1023u) & ~1023u;
    char* sm = smraw + (sbu - su);

    const int e0 = blockIdx.x * 128;
    const int m0 = blockIdx.y * 128;
    const __nv_bfloat16* Ag = g_as + (size_t)m0 * TKv;
    const __nv_bfloat16* Bg = g_ws[3] + (size_t)e0 * TKv;
    gemm_tile(Ag, Bg, out, (const int*)0, 0, m0, e0, sm, sbu);
}

// ---------------------------------------------------------------------------
// Prep: fp32 Q and K [n][1024] -> bf16 hi/lo [bh][s][64]; grid 4096
// ---------------------------------------------------------------------------
__global__ __launch_bounds__(256) void qk_prep2()
{
    const int sel = blockIdx.x >> 11;
    const float* src = sel ? g_k : g_q;
    __nv_bfloat16* dh = sel ? g_kh : g_qh;
    __nv_bfloat16* dl = sel ? g_kl : g_ql;

    size_t L = (((size_t)(blockIdx.x & 2047)) * 256 + threadIdx.x) * 8;
    int bh = (int)(L >> 17);
    int rem = (int)(L & 131071);
    int s = rem >> 6;
    int dk = rem & 63;
    int b = bh >> 4, h = bh & 15;
    size_t sidx = ((size_t)(b * Sv + s)) * Dv + h * 64 + dk;
    float4 v0 = *(const float4*)(src + sidx);
    float4 v1 = *(const float4*)(src + sidx + 4);

    float vv[8] = {v0.x, v0.y, v0.z, v0.w, v1.x, v1.y, v1.z, v1.w};
    uint32_t hu[4], lu[4];
    #pragma unroll
    for (int i = 0; i < 4; ++i) {
        __nv_bfloat162 hp = __floats2bfloat162_rn(vv[2*i], vv[2*i+1]);
        float r0 = __bfloat162float(hp.x), r1 = __bfloat162float(hp.y);
        __nv_bfloat162 lp = __floats2bfloat162_rn(vv[2*i] - r0, vv[2*i+1] - r1);
        hu[i] = *(uint32_t*)&hp;
        lu[i] = *(uint32_t*)&lp;
    }
    *(uint4*)(dh + L) = make_uint4(hu[0], hu[1], hu[2], hu[3]);
    *(uint4*)(dl + L) = make_uint4(lu[0], lu[1], lu[2], lu[3]);
}

// ---------------------------------------------------------------------------
// Prep: fp32 V -> bf16 hi/lo transposed [bh][dk][s]; grid (S/64, BH)
// ---------------------------------------------------------------------------
__global__ __launch_bounds__(256) void v_prep()
{
    __shared__ float sv[64][65];
    const int tid = threadIdx.x;
    const int st = blockIdx.x, bh = blockIdx.y;
    const int s0 = st * 64;
    const int b = bh >> 4, h = bh & 15;

    #pragma unroll
    for (int p = 0; p < 4; ++p) {
        int idx = p * 256 + tid;
        int r = idx >> 4, c = (idx & 15) * 4;
        float4 v = *(const float4*)(g_v + ((size_t)(b * Sv + s0 + r)) * Dv + h * 64 + c);
        sv[r][c] = v.x; sv[r][c+1] = v.y; sv[r][c+2] = v.z; sv[r][c+3] = v.w;
    }
    __syncthreads();

    int dk = tid >> 2;
    int t0 = (tid & 3) * 16;
    uint32_t hu[8], lu[8];
    #pragma unroll
    for (int i = 0; i < 8; ++i) {
        float a = sv[t0 + 2*i][dk], c = sv[t0 + 2*i + 1][dk];
        __nv_bfloat162 hp = __floats2bfloat162_rn(a, c);
        float r0 = __bfloat162float(hp.x), r1 = __bfloat162float(hp.y);
        __nv_bfloat162 lp = __floats2bfloat162_rn(a - r0, c - r1);
        hu[i] = *(uint32_t*)&hp;
        lu[i] = *(uint32_t*)&lp;
    }
    size_t o = ((size_t)bh * 64 + dk) * Sv + s0 + t0;
    *(uint4*)(g_vh + o)     = make_uint4(hu[0], hu[1], hu[2], hu[3]);
    *(uint4*)(g_vh + o + 8) = make_uint4(hu[4], hu[5], hu[6], hu[7]);
    *(uint4*)(g_vl + o)     = make_uint4(lu[0], lu[1], lu[2], lu[3]);
    *(uint4*)(g_vl + o + 8) = make_uint4(lu[4], lu[5], lu[6], lu[7]);
}

// ---------------------------------------------------------------------------
// Flash attention on mma.sync, 3-term split for QK^T and PV.
// CTA: 128 q rows x (b,h). kv tiles of 64, cp.async double-buffered.
// ---------------------------------------------------------------------------
__device__ __forceinline__ void attn_load_tile(
    uint32_t sb, uint32_t oKh, uint32_t oKl, uint32_t oVh, uint32_t oVl,
    int bh, int j, int buf, int tid)
{
    const char* kh = (const char*)(g_kh + ((size_t)bh * Sv + j * 64) * 64);
    const char* kl = (const char*)(g_kl + ((size_t)bh * Sv + j * 64) * 64);
    #pragma unroll
    for (int p = 0; p < 2; ++p) {
        int idx = p * 256 + tid;
        int r = idx >> 3, c = idx & 7;
        uint32_t so = SW128((uint32_t)(r * 128 + c * 16));
        uint32_t bo = (uint32_t)(buf * 8192);
        cpa16(sb + oKh + bo + so, kh + idx * 16);
        cpa16(sb + oKl + bo + so, kl + idx * 16);
        const char* vh = (const char*)(g_vh + ((size_t)bh * 64 + r) * Sv + j * 64);
        const char* vl = (const char*)(g_vl + ((size_t)bh * 64 + r) * Sv + j * 64);
        cpa16(sb + oVh + bo + so, vh + c * 16);
        cpa16(sb + oVl + bo + so, vl + c * 16);
    }
}

__global__ __launch_bounds__(256, 1) void attn_mma()
{
    extern __shared__ char smraw[];
    uint32_t su = smem_to_u32(smraw);
    uint32_t sb = (su + 1023u) & ~1023u;
    const uint32_t oQh = 0, oQl = 16384;
    const uint32_t oKh = 32768, oKl = 49152;
    const uint32_t oVh = 65536, oVl = 81920;

    const int tid = threadIdx.x;
    const int wid = tid >> 5, lane = tid & 31;
    const int g2 = lane >> 2, t4 = lane & 3;
    const int lrow = lane & 15;
    const int lkoff = ((lane >> 4) & 1) * 16;

    const int qt = gridDim.x - 1 - blockIdx.x;
    const int h = blockIdx.y, b = blockIdx.z;
    const int bh = b * Hv + h;
    const int q0 = qt * 128;
    const int jmax = 2 * qt + 1;

    {
        const char* qh = (const char*)(g_qh + ((size_t)bh * Sv + q0) * 64);
        const char* ql = (const char*)(g_ql + ((size_t)bh * Sv + q0) * 64);
        #pragma unroll
        for (int p = 0; p < 4; ++p) {
            int idx = p * 256 + tid;
            uint32_t so = SW128((uint32_t)(idx * 16));
            cpa16(sb + oQh + so, qh + idx * 16);
            cpa16(sb + oQl + so, ql + idx * 16);
        }
        attn_load_tile(sb, oKh, oKl, oVh, oVl, bh, 0, 0, tid);
        CP_COMMIT();
    }

    float m0 = -1e30f, m1 = -1e30f, l0 = 0.f, l1 = 0.f;
    float oacc[8][4];
    #pragma unroll
    for (int i = 0; i < 8; ++i)
        #pragma unroll
        for (int c = 0; c < 4; ++c) oacc[i][c] = 0.f;

    for (int j = 0; j <= jmax; ++j) {
        const int cur = j & 1;
        if (j < jmax) {
            attn_load_tile(sb, oKh, oKl, oVh, oVl, bh, j + 1, cur ^ 1, tid);
            CP_COMMIT();
            CP_WAIT(1);
        } else {
            CP_WAIT(0);
        }
        __syncthreads();

        // S = Qhi*Khi + Qhi*Klo + Qlo*Khi, fragments loaded once per ks
        float sacc[8][4];
        #pragma unroll
        for (int i = 0; i < 8; ++i)
            #pragma unroll
            for (int c = 0; c < 4; ++c) sacc[i][c] = 0.f;
        {
            const uint32_t kb = (uint32_t)(cur * 8192);
            const uint32_t khB = sb + oKh + kb, klB = sb + oKl + kb;
            #pragma unroll
            for (int ks = 0; ks < 4; ++ks) {
                uint32_t kbyte = (uint32_t)(ks * 32 + lkoff);
                uint32_t aoff = SW128((uint32_t)((wid * 16 + lrow) * 128) + kbyte);
                uint32_t ah[4], al[4];
                ldm_x4(ah, sb + oQh + aoff);
                ldm_x4(al, sb + oQl + aoff);
                #pragma unroll
                for (int bn4 = 0; bn4 < 4; ++bn4) {
                    uint32_t boff = SW128((uint32_t)((bn4 * 16 + lrow) * 128) + kbyte);
                    uint32_t bh_[4], bl_[4];
                    ldm_x4(bh_, khB + boff);
                    ldm_x4(bl_, klB + boff);
                    uint32_t bhl[2] = {bh_[0], bh_[2]}, bhh[2] = {bh_[1], bh_[3]};
                    uint32_t bll[2] = {bl_[0], bl_[2]}, blh[2] = {bl_[1], bl_[3]};
                    mma_16816(sacc[2 * bn4],     ah, bhl);
                    mma_16816(sacc[2 * bn4 + 1], ah, bhh);
                    mma_16816(sacc[2 * bn4],     ah, bll);
                    mma_16816(sacc[2 * bn4 + 1], ah, blh);
                    mma_16816(sacc[2 * bn4],     al, bhl);
                    mma_16816(sacc[2 * bn4 + 1], al, bhh);
                }
            }
        }

        if (j >= 2 * qt) {
            int r0 = q0 + wid * 16 + g2;
            #pragma unroll
            for (int bn = 0; bn < 8; ++bn) {
                int col = j * 64 + bn * 8 + 2 * t4;
                #pragma unroll
                for (int c = 0; c < 4; ++c) {
                    int row = r0 + ((c >= 2) ? 8 : 0);
                    if (col + (c & 1) > row) sacc[bn][c] = -1e30f;
                }
            }
        }

        float tm0 = -1e30f, tm1 = -1e30f;
        #pragma unroll
        for (int bn = 0; bn < 8; ++bn) {
            tm0 = fmaxf(tm0, fmaxf(sacc[bn][0], sacc[bn][1]));
            tm1 = fmaxf(tm1, fmaxf(sacc[bn][2], sacc[bn][3]));
        }
        tm0 = fmaxf(tm0, __shfl_xor_sync(0xffffffffu, tm0, 1));
        tm0 = fmaxf(tm0, __shfl_xor_sync(0xffffffffu, tm0, 2));
        tm1 = fmaxf(tm1, __shfl_xor_sync(0xffffffffu, tm1, 1));
        tm1 = fmaxf(tm1, __shfl_xor_sync(0xffffffffu, tm1, 2));
        float mn0 = fmaxf(m0, tm0), mn1 = fmaxf(m1, tm1);
        float sc0 = __expf(m0 - mn0), sc1 = __expf(m1 - mn1);
        float rs0 = 0.f, rs1 = 0.f;
        #pragma unroll
        for (int bn = 0; bn < 8; ++bn) {
            sacc[bn][0] = __expf(sacc[bn][0] - mn0);
            sacc[bn][1] = __expf(sacc[bn][1] - mn0);
            sacc[bn][2] = __expf(sacc[bn][2] - mn1);
            sacc[bn][3] = __expf(sacc[bn][3] - mn1);
            rs0 += sacc[bn][0] + sacc[bn][1];
            rs1 += sacc[bn][2] + sacc[bn][3];
        }
        rs0 += __shfl_xor_sync(0xffffffffu, rs0, 1);
        rs0 += __shfl_xor_sync(0xffffffffu, rs0, 2);
        rs1 += __shfl_xor_sync(0xffffffffu, rs1, 1);
        rs1 += __shfl_xor_sync(0xffffffffu, rs1, 2);
        l0 = l0 * sc0 + rs0;
        l1 = l1 * sc1 + rs1;
        m0 = mn0; m1 = mn1;
        #pragma unroll
        for (int bn = 0; bn < 8; ++bn) {
            oacc[bn][0] *= sc0; oacc[bn][1] *= sc0;
            oacc[bn][2] *= sc1; oacc[bn][3] *= sc1;
        }

        // O += Phi*Vhi + Phi*Vlo + Plo*Vhi
        {
            uint32_t vhB = sb + oVh + (uint32_t)(cur * 8192);
            uint32_t vlB = sb + oVl + (uint32_t)(cur * 8192);
            #pragma unroll
            for (int ks = 0; ks < 4; ++ks) {
                uint32_t ah[4], al[4];
                #pragma unroll
                for (int q = 0; q < 4; ++q) {
                    int tl = 2 * ks + (q >> 1);
                    int c0 = (q & 1) * 2;
                    float a = sacc[tl][c0], c = sacc[tl][c0 + 1];
                    __nv_bfloat162 hp = __floats2bfloat162_rn(a, c);
                    float r0 = __bfloat162float(hp.x), r1 = __bfloat162float(hp.y);
                    __nv_bfloat162 lp = __floats2bfloat162_rn(a - r0, c - r1);
                    ah[q] = *(uint32_t*)&hp;
                    al[q] = *(uint32_t*)&lp;
                }
                uint32_t kbyte = (uint32_t)(ks * 32 + lkoff);
                #pragma unroll
                for (int bn4 = 0; bn4 < 4; ++bn4) {
                    uint32_t bH[4], bL[4];
                    uint32_t off = SW128((uint32_t)((bn4 * 16 + lrow) * 128) + kbyte);
                    ldm_x4(bH, vhB + off);
                    ldm_x4(bL, vlB + off);
                    uint32_t bHl[2] = {bH[0], bH[2]}, bHh[2] = {bH[1], bH[3]};
                    uint32_t bLl[2] = {bL[0], bL[2]}, bLh[2] = {bL[1], bL[3]};
                    mma_16816(oacc[2 * bn4],     ah, bHl);
                    mma_16816(oacc[2 * bn4 + 1], ah, bHh);
                    mma_16816(oacc[2 * bn4],     ah, bLl);
                    mma_16816(oacc[2 * bn4 + 1], ah, bLh);
                    mma_16816(oacc[2 * bn4],     al, bHl);
                    mma_16816(oacc[2 * bn4 + 1], al, bHh);
                }
            }
        }
        __syncthreads();
    }

    float il0 = 1.f / l0, il1 = 1.f / l1;
    int row0 = q0 + wid * 16 + g2;
    size_t n0 = (size_t)b * Sv + row0;
    #pragma unroll
    for (int bn = 0; bn < 8; ++bn) {
        int col = h * 64 + bn * 8 + 2 * t4;
        #pragma unroll
        for (int half = 0; half < 2; ++half) {
            float v0 = oacc[bn][half * 2]     * (half ? il1 : il0);
            float v1 = oacc[bn][half * 2 + 1] * (half ? il1 : il0);
            __nv_bfloat162 hp = __floats2bfloat162_rn(v0, v1);
            float r0 = __bfloat162float(hp.x), r1 = __bfloat162float(hp.y);
            __nv_bfloat162 lp = __floats2bfloat162_rn(v0 - r0, v1 - r1);
            size_t base = (n0 + half * 8) * TKv + col;
            *(uint32_t*)(g_as + base)        = *(uint32_t*)&hp;
            *(uint32_t*)(g_as + base + 1024) = *(uint32_t*)&hp;
            *(uint32_t*)(g_as + base + 2048) = *(uint32_t*)&lp;
        }
    }
}

// ---------------------------------------------------------------------------
extern "C" void kernel_launch(void* const* d_in, const int* in_sizes, int n_in,
                              void* d_out, int out_size)
{
    const float* x  = (const float*)d_in[0];
    const int*   tp = (const int*)d_in[1];
    const float* w0 = (const float*)d_in[2];
    const float* w1 = (const float*)d_in[3];
    const float* w2 = (const float*)d_in[4];
    const float* w3 = (const float*)d_in[5];
    float* out = (float*)d_out;

    float *pq, *pk, *pv;
    cudaGetSymbolAddress((void**)&pq, g_q);
    cudaGetSymbolAddress((void**)&pk, g_k);
    cudaGetSymbolAddress((void**)&pv, g_v);

    const int gemm_smem = 65536 + 1024;
    cudaFuncSetAttribute(gemm_qkv, cudaFuncAttributeMaxDynamicSharedMemorySize,
                         gemm_smem);
    cudaFuncSetAttribute(gemm_o, cudaFuncAttributeMaxDynamicSharedMemorySize,
                         gemm_smem);
    const int attn_smem = 96 * 1024 + 1024;
    cudaFuncSetAttribute(attn_mma, cudaFuncAttributeMaxDynamicSharedMemorySize,
                         attn_smem);

    // 1) splits (2 launches)
    xsplit_kernel<<<(Nv * Dv) / (4 * 256), 256>>>(x);
    wsplit_kernel<<<4 * (Dv * Dv) / (4 * 256), 256>>>(w0, w1, w2, w3);

    // 2) fused QKV projection
    gemm_qkv<<<dim3(24, Nv / 128), 256, gemm_smem>>>(tp, pq, pk, pv);

    // 3) attention operand prep (2 launches)
    qk_prep2<<<4096, 256>>>();
    v_prep<<<dim3(Sv / 64, BHv), 256>>>();

    // 4) attention
    attn_mma<<<dim3(Sv / 128, Hv, Bv), 256, attn_smem>>>();

    // 5) output projection
    gemm_o<<<dim3(Dv / 128, Nv / 128), 256, gemm_smem>>>(out);
}